// round 6
// baseline (speedup 1.0000x reference)
#include <cuda_runtime.h>
#include <cstdint>

#define CROP 8
#define W    512
#define CW   496
#define TX   16
#define TY   16
#define NT   768               /* 256 pixels x 3 channels */
#define SW   22
#define STAGEF (SW*SW*3)       /* 1452 floats per view tile */
#define PLANE  (W*W*3)
#define NSTG 6                 /* view ring depth */
#define VALS_OFF (NSTG*STAGEF)                   /* floats */
#define RED_OFF  (VALS_OFF + 48*NT)              /* floats */
#define SMEM_FLOATS (RED_OFF + 32)
#define SMEM_BYTES (SMEM_FLOATS*4)               /* 182432 B */

__device__ double g_cl, g_gx, g_gy;

__global__ void k_init() { g_cl = 0.0; g_gx = 0.0; g_gy = 0.0; }

__device__ __forceinline__ int k_epoch(int e) {
  if (e < 200) return 0;
  if (e < 2300) return ((e - 200) / 100) * 2;
  return 44;
}

// ascending bitonic sort, fully unrolled (numerics proven rounds 3-4)
template <int N>
__device__ __forceinline__ void bsort(float (&a)[N]) {
#pragma unroll
  for (int k = 2; k <= N; k <<= 1) {
#pragma unroll
    for (int j = k >> 1; j > 0; j >>= 1) {
#pragma unroll
      for (int i = 0; i < N; i++) {
        int l = i ^ j;
        if (l > i) {
          float x = a[i], y = a[l];
          float lo = fminf(x, y), hi = fmaxf(x, y);
          bool up = ((i & k) == 0);
          a[i] = up ? lo : hi;
          a[l] = up ? hi : lo;
        }
      }
    }
  }
}

__device__ __forceinline__ void cpasync4(uint32_t dst, const float* src) {
  asm volatile("cp.async.ca.shared.global [%0], [%1], 4;\n" :: "r"(dst), "l"(src));
}
__device__ __forceinline__ void cp_commit() {
  asm volatile("cp.async.commit_group;\n" ::);
}
__device__ __forceinline__ void cp_wait4() {
  asm volatile("cp.async.wait_group 4;\n" ::);
}

// bilinear sample of channel ch at (ty,tx) from a staged tile, minus center
__device__ __forceinline__ float bilin_diff(const float* __restrict__ stg,
                                            float ty, float tx,
                                            int row0, int col0, int ch, float cen) {
  float fy = floorf(ty), fx = floorf(tx);
  float wy = ty - fy, wx = tx - fx;
  int iy = (int)fy - row0;
  int ix = (int)fx - col0;
  int base = (iy * SW + ix) * 3 + ch;
  float v00 = stg[base],      v01 = stg[base + 3];
  float v10 = stg[base + 66], v11 = stg[base + 69];
  float a0 = v00 + wx * (v01 - v00);
  float a1 = v10 + wx * (v11 - v10);
  float r  = a0 + wy * (a1 - a0);
  return fabsf(r - cen);
}

// stage view order i (ring): i=0 -> center view 24; i in [1..24] -> view i-1;
// i in [25..48] -> view i. (so vals slot s = i-1 maps to view n=(s<24)?s:s+1)
__device__ __forceinline__ int view_of(int i) {
  return (i == 0) ? 24 : ((i <= 24) ? (i - 1) : i);
}

__global__ __launch_bounds__(NT, 1)
void k_main(const float* __restrict__ pred, const float* __restrict__ xin,
            const int* __restrict__ ep) {
  extern __shared__ float sm[];
  float* stage = sm;                 // NSTG tiles of STAGEF floats
  float* vals  = sm + VALS_OFF;      // vals[s*NT + tid], fp32
  float* red   = sm + RED_OFF;

  const int tid = threadIdx.x;
  const int ch  = tid >> 8;          // 0..2
  const int pix = tid & 255;
  const int lx = pix & 15, ly = pix >> 4;
  const int gx0 = CROP + blockIdx.x * TX;
  const int gy0 = CROP + blockIdx.y * TY;
  const int b = blockIdx.z;
  const int gx = gx0 + lx, gy = gy0 + ly;
  const int row0 = gy0 - 3, col0 = gx0 - 3;
  const float* xb = xin + (size_t)b * 49 * PLANE;

  const float p = __ldg(pred + ((size_t)b * W + gy) * W + gx);
  const float fgy = (float)gy, fgx = (float)gx;
  const int epoch = ep ? ep[0] : 1000;
  const int K = 49 - k_epoch(epoch);

  // per-thread staging offsets (elements tid and tid+NT of the tile)
  const int sidx0 = tid, sidx1 = tid + NT;
  const int r0 = sidx0 / 66, c0 = sidx0 - r0 * 66;
  const int r1 = sidx1 / 66, c1 = sidx1 - r1 * 66;
  const size_t goff0 = (size_t)(row0 + r0) * (W * 3) + (size_t)col0 * 3 + c0;
  const size_t goff1 = (size_t)(row0 + r1) * (W * 3) + (size_t)col0 * 3 + c1;
  const bool ok1 = (sidx1 < STAGEF);

  const uint32_t stg_s = (uint32_t)__cvta_generic_to_shared(stage);

  // ---- prologue: issue views i=0..4, one commit group per view ----
#pragma unroll
  for (int i = 0; i < 5; i++) {
    const float* pl = xb + (size_t)view_of(i) * PLANE;
    uint32_t dst = stg_s + (uint32_t)(i * STAGEF) * 4u;
    cpasync4(dst + (uint32_t)sidx0 * 4u, pl + goff0);
    if (ok1) cpasync4(dst + (uint32_t)sidx1 * 4u, pl + goff1);
    cp_commit();
  }

  float cen = 0.f;

  for (int i = 0; i < 49; i++) {
    cp_wait4();            // own copies for view i complete (<=4 groups pending)
    __syncthreads();       // all threads' copies visible; all done computing i-1

    // issue view i+5 into buffer (i+5)%6 == (i-1)%6 (free: compute i-1 done).
    // Always commit (empty group in tail) so wait_group 4 stays correct.
    if (i + 5 < 49) {
      const float* pl = xb + (size_t)view_of(i + 5) * PLANE;
      uint32_t dst = stg_s + (uint32_t)(((i + 5) % NSTG) * STAGEF) * 4u;
      cpasync4(dst + (uint32_t)sidx0 * 4u, pl + goff0);
      if (ok1) cpasync4(dst + (uint32_t)sidx1 * 4u, pl + goff1);
    }
    cp_commit();

    const float* stg = stage + (i % NSTG) * STAGEF;
    if (i == 0) {
      cen = stg[((ly + 3) * SW + (lx + 3)) * 3 + ch];
    } else {
      int s = i - 1;
      int n = (s < 24) ? s : s + 1;
      float du = (float)(n / 7 - 3), dv = (float)(n % 7 - 3);
      float ty = __fadd_rn(fgy, __fmul_rn(p, du));
      float tx = __fadd_rn(fgx, __fmul_rn(p, dv));
      vals[s * NT + tid] = bilin_diff(stg, ty, tx, row0, col0, ch, cen);
    }
  }

  // ---------------- phase 2: rank select + masked sum (one channel/thread) ---
  float mysum = 0.f;
  if (K == 33) {
    float A[32], B[16];
#pragma unroll
    for (int s = 0; s < 32; s++) A[s] = vals[s * NT + tid];
#pragma unroll
    for (int s = 0; s < 16; s++) B[s] = vals[(32 + s) * NT + tid];
    bsort<32>(A);
    bsort<16>(B);
    // t = rank-32 (1-indexed) of A(32) U B(16): min over i+j=32 of max(A_i,B_j)
    float t = A[31];
#pragma unroll
    for (int i2 = 16; i2 <= 31; i2++) t = fminf(t, fmaxf(A[i2 - 1], B[31 - i2]));
    // >=16 elements of A are <= t guaranteed: sum A[0..15] unconditionally
    float s0 = 0.f, s1 = 0.f;
#pragma unroll
    for (int s = 0; s < 16; s++) { s0 += A[s]; s1 += A[16 + s] <= t ? A[16 + s] : 0.f; }
#pragma unroll
    for (int s = 0; s < 16; s++) s1 += (B[s] <= t) ? B[s] : 0.f;
    mysum = s0 + s1;
  } else {
    // generic rank r = K-1 among 48 non-center values (not taken @epoch 1000)
    int r = K - 1;
    float t = 3.0e38f;
    for (int a = 0; a < 48; a++) {
      float va = vals[a * NT + tid];
      int cnt = 0;
      for (int q = 0; q < 48; q++) cnt += (vals[q * NT + tid] <= va) ? 1 : 0;
      if (cnt >= r) t = fminf(t, va);
    }
    for (int a = 0; a < 48; a++) {
      float va = vals[a * NT + tid];
      mysum += (va <= t) ? va : 0.f;
    }
  }

  // block reduce -> one double atomic
#pragma unroll
  for (int o = 16; o > 0; o >>= 1) mysum += __shfl_down_sync(0xffffffffu, mysum, o);
  if ((tid & 31) == 0) red[tid >> 5] = mysum;
  __syncthreads();
  if (tid == 0) {
    float tot = 0.f;
    for (int w2 = 0; w2 < NT / 32; w2++) tot += red[w2];
    atomicAdd(&g_cl, (double)tot);
  }
}

// ---------------- edge-aware smoothness, split by direction ----------------
__global__ void k_gradx(const float* __restrict__ pred, const float* __restrict__ xin) {
  int idx = blockIdx.x * 256 + threadIdx.x;
  float sx = 0.f;
  if (idx < 2 * CW * CW) {
    int b = idx / (CW * CW);
    int rem = idx - b * (CW * CW);
    int y = CROP + rem / CW;
    int x = CROP + rem % CW;
    if (x < CROP + CW - 1) {
      const float* I = xin + ((size_t)b * 49 + 24) * PLANE;
      const float* D = pred + (size_t)b * W * W;
      size_t o = (size_t)y * W + x;
      float a = fabsf(I[(o + 1) * 3] - I[o * 3]) +
                fabsf(I[(o + 1) * 3 + 1] - I[o * 3 + 1]) +
                fabsf(I[(o + 1) * 3 + 2] - I[o * 3 + 2]);
      sx = expf(-50.f * a) * fabsf(D[o + 1] - D[o]);
    }
  }
#pragma unroll
  for (int o2 = 16; o2 > 0; o2 >>= 1) sx += __shfl_down_sync(0xffffffffu, sx, o2);
  __shared__ float rx[8];
  int tid = threadIdx.x;
  if ((tid & 31) == 0) rx[tid >> 5] = sx;
  __syncthreads();
  if (tid == 0) {
    float a = 0.f;
    for (int w2 = 0; w2 < 8; w2++) a += rx[w2];
    atomicAdd(&g_gx, (double)a);
  }
}

__global__ void k_grady(const float* __restrict__ pred, const float* __restrict__ xin) {
  int idx = blockIdx.x * 256 + threadIdx.x;
  float sy = 0.f;
  if (idx < 2 * CW * CW) {
    int b = idx / (CW * CW);
    int rem = idx - b * (CW * CW);
    int y = CROP + rem / CW;
    int x = CROP + rem % CW;
    if (y < CROP + CW - 1) {
      const float* I = xin + ((size_t)b * 49 + 24) * PLANE;
      const float* D = pred + (size_t)b * W * W;
      size_t o = (size_t)y * W + x;
      float a = fabsf(I[(o + W) * 3] - I[o * 3]) +
                fabsf(I[(o + W) * 3 + 1] - I[o * 3 + 1]) +
                fabsf(I[(o + W) * 3 + 2] - I[o * 3 + 2]);
      sy = expf(-50.f * a) * fabsf(D[o + W] - D[o]);
    }
  }
#pragma unroll
  for (int o2 = 16; o2 > 0; o2 >>= 1) sy += __shfl_down_sync(0xffffffffu, sy, o2);
  __shared__ float ry[8];
  int tid = threadIdx.x;
  if ((tid & 31) == 0) ry[tid >> 5] = sy;
  __syncthreads();
  if (tid == 0) {
    float c = 0.f;
    for (int w2 = 0; w2 < 8; w2++) c += ry[w2];
    atomicAdd(&g_gy, (double)c);
  }
}

__global__ void k_fin(const int* __restrict__ ep, float* __restrict__ out) {
  int epoch = ep ? ep[0] : 1000;
  int K = 49 - k_epoch(epoch);
  double mcl = g_cl / ((double)K * 6.0 * 496.0 * 496.0);
  double den = 2.0 * 496.0 * 495.0;
  double gl = 0.5 * (g_gx / den + g_gy / den);
  out[0] = (float)(mcl + 0.1 * gl);
}

extern "C" void kernel_launch(void* const* d_in, const int* in_sizes, int n_in,
                              void* d_out, int out_size) {
  const float* pred = (const float*)d_in[0];
  const float* x    = (const float*)d_in[1];
  const int*   ep   = (n_in >= 3) ? (const int*)d_in[2] : nullptr;

  cudaFuncSetAttribute(k_main, cudaFuncAttributeMaxDynamicSharedMemorySize, SMEM_BYTES);

  k_init<<<1, 1>>>();
  k_gradx<<<(2 * CW * CW + 255) / 256, 256>>>(pred, x);
  k_grady<<<(2 * CW * CW + 255) / 256, 256>>>(pred, x);
  dim3 grid(31, 31, 2);
  k_main<<<grid, NT, SMEM_BYTES>>>(pred, x, ep);
  k_fin<<<1, 1>>>(ep, (float*)d_out);
}

// round 8
// speedup vs baseline: 1.0669x; 1.0669x over previous
#include <cuda_runtime.h>
#include <cstdint>

#define CROP 8
#define W    512
#define CW   496
#define TX   16
#define TY   8
#define NPIX 128
#define NT   384               /* 128 pixels x 3 channels */
#define SW   22
#define SH   14                /* TY + 6 */
#define STAGEF (SH*SW*3)       /* 924 floats per view tile */
#define PLANE  (W*W*3)
#define VALS_OFF (2*STAGEF)                      /* floats */
#define RED_OFF  (VALS_OFF + 48*NT)              /* floats */
#define SMEM_FLOATS (RED_OFF + 16)
#define SMEM_BYTES (SMEM_FLOATS*4)               /* 81,184 B -> 2 blocks/SM */

__device__ double g_cl, g_gx, g_gy;

__global__ void k_init() { g_cl = 0.0; g_gx = 0.0; g_gy = 0.0; }

__device__ __forceinline__ int k_epoch(int e) {
  if (e < 200) return 0;
  if (e < 2300) return ((e - 200) / 100) * 2;
  return 44;
}

// ascending bitonic sort, fully unrolled (numerics proven rounds 3-4)
template <int N>
__device__ __forceinline__ void bsort(float (&a)[N]) {
#pragma unroll
  for (int k = 2; k <= N; k <<= 1) {
#pragma unroll
    for (int j = k >> 1; j > 0; j >>= 1) {
#pragma unroll
      for (int i = 0; i < N; i++) {
        int l = i ^ j;
        if (l > i) {
          float x = a[i], y = a[l];
          float lo = fminf(x, y), hi = fmaxf(x, y);
          bool up = ((i & k) == 0);
          a[i] = up ? lo : hi;
          a[l] = up ? hi : lo;
        }
      }
    }
  }
}

// bilinear sample of channel ch at (ty,tx) from a staged tile, minus center
__device__ __forceinline__ float bilin_diff(const float* __restrict__ stg,
                                            float ty, float tx,
                                            int row0, int col0, int ch, float cen) {
  float fy = floorf(ty), fx = floorf(tx);
  float wy = ty - fy, wx = tx - fx;
  int iy = (int)fy - row0;
  int ix = (int)fx - col0;
  int base = (iy * SW + ix) * 3 + ch;
  float v00 = stg[base],      v01 = stg[base + 3];
  float v10 = stg[base + 66], v11 = stg[base + 69];
  float a0 = v00 + wx * (v01 - v00);
  float a1 = v10 + wx * (v11 - v10);
  float r  = a0 + wy * (a1 - a0);
  return fabsf(r - cen);
}

__global__ __launch_bounds__(NT, 2)
void k_main(const float* __restrict__ pred, const float* __restrict__ xin,
            const int* __restrict__ ep) {
  extern __shared__ float sm[];
  float* stage = sm;                 // 2 tiles of STAGEF floats
  float* vals  = sm + VALS_OFF;      // vals[s*NT + tid], fp32
  float* red   = sm + RED_OFF;

  const int tid = threadIdx.x;
  const int ch  = tid / NPIX;        // 0..2
  const int pix = tid - ch * NPIX;
  const int lx = pix & 15, ly = pix >> 4;
  const int gx0 = CROP + blockIdx.x * TX;
  const int gy0 = CROP + blockIdx.y * TY;
  const int b = blockIdx.z;
  const int gx = gx0 + lx, gy = gy0 + ly;
  const int row0 = gy0 - 3, col0 = gx0 - 3;
  const float* xb = xin + (size_t)b * 49 * PLANE;

  const float p = __ldg(pred + ((size_t)b * W + gy) * W + gx);
  const float fgy = (float)gy, fgx = (float)gx;
  const int epoch = ep ? ep[0] : 1000;
  const int K = 49 - k_epoch(epoch);

  // per-thread staging slots (elements tid, tid+NT, tid+2NT of the 924-float tile)
  const int sidx0 = tid, sidx1 = tid + NT, sidx2 = tid + 2 * NT;
  const int r0 = sidx0 / 66, c0 = sidx0 - r0 * 66;
  const int r1 = sidx1 / 66, c1 = sidx1 - r1 * 66;
  const int r2 = sidx2 / 66, c2 = sidx2 - r2 * 66;
  const size_t goff0 = (size_t)(row0 + r0) * (W * 3) + (size_t)col0 * 3 + c0;
  const size_t goff1 = (size_t)(row0 + r1) * (W * 3) + (size_t)col0 * 3 + c1;
  const size_t goff2 = (size_t)(row0 + r2) * (W * 3) + (size_t)col0 * 3 + c2;
  const bool ok2 = (sidx2 < STAGEF);   // sidx1 always < 924

  // ---- stage center view (24) into stage[0] ----
  {
    const float* pl = xb + (size_t)24 * PLANE;
    stage[sidx0] = __ldg(pl + goff0);
    stage[sidx1] = __ldg(pl + goff1);
    if (ok2) stage[sidx2] = __ldg(pl + goff2);
  }
  __syncthreads();
  const float cen = stage[((ly + 3) * SW + (lx + 3)) * 3 + ch];

  // ---- prefetch pair 0 (views s=0,1 -> n=0,1) ----
  float a0, a1, a2, b0, b1, b2;
  {
    const float* pl0 = xb;                       // n=0
    const float* pl1 = xb + (size_t)1 * PLANE;   // n=1
    a0 = __ldg(pl0 + goff0);
    a1 = __ldg(pl0 + goff1);
    a2 = ok2 ? __ldg(pl0 + goff2) : 0.f;
    b0 = __ldg(pl1 + goff0);
    b1 = __ldg(pl1 + goff1);
    b2 = ok2 ? __ldg(pl1 + goff2) : 0.f;
  }

  for (int j = 0; j < 24; j++) {
    __syncthreads();                 // prior reads of stage complete
    stage[sidx0] = a0;
    stage[sidx1] = a1;
    if (ok2) stage[sidx2] = a2;
    stage[STAGEF + sidx0] = b0;
    stage[STAGEF + sidx1] = b1;
    if (ok2) stage[STAGEF + sidx2] = b2;
    __syncthreads();                 // staged pair visible

    if (j < 23) {                    // prefetch pair j+1 (consumed next iter)
      int s0n = 2 * (j + 1);
      int n0 = (s0n < 24) ? s0n : s0n + 1;
      int n1 = (s0n + 1 < 24) ? s0n + 1 : s0n + 2;
      const float* pl0 = xb + (size_t)n0 * PLANE;
      const float* pl1 = xb + (size_t)n1 * PLANE;
      a0 = __ldg(pl0 + goff0);
      a1 = __ldg(pl0 + goff1);
      a2 = ok2 ? __ldg(pl0 + goff2) : 0.f;
      b0 = __ldg(pl1 + goff0);
      b1 = __ldg(pl1 + goff1);
      b2 = ok2 ? __ldg(pl1 + goff2) : 0.f;
    }

    // compute views s=2j, 2j+1
    {
      int s = 2 * j;
      int n = (s < 24) ? s : s + 1;
      float du = (float)(n / 7 - 3), dv = (float)(n % 7 - 3);
      float ty = __fadd_rn(fgy, __fmul_rn(p, du));
      float tx = __fadd_rn(fgx, __fmul_rn(p, dv));
      vals[s * NT + tid] = bilin_diff(stage, ty, tx, row0, col0, ch, cen);
    }
    {
      int s = 2 * j + 1;
      int n = (s < 24) ? s : s + 1;
      float du = (float)(n / 7 - 3), dv = (float)(n % 7 - 3);
      float ty = __fadd_rn(fgy, __fmul_rn(p, du));
      float tx = __fadd_rn(fgx, __fmul_rn(p, dv));
      vals[s * NT + tid] = bilin_diff(stage + STAGEF, ty, tx, row0, col0, ch, cen);
    }
  }

  // ---------------- phase 2: rank select + masked sum (one channel/thread) ---
  float mysum = 0.f;
  if (K == 33) {
    float A[32], B[16];
#pragma unroll
    for (int s = 0; s < 32; s++) A[s] = vals[s * NT + tid];
#pragma unroll
    for (int s = 0; s < 16; s++) B[s] = vals[(32 + s) * NT + tid];
    bsort<32>(A);
    bsort<16>(B);
    // t = rank-32 (1-indexed) of A(32) U B(16): min over i+j=32 of max(A_i,B_j)
    float t = A[31];
#pragma unroll
    for (int i2 = 16; i2 <= 31; i2++) t = fminf(t, fmaxf(A[i2 - 1], B[31 - i2]));
    // >=16 elements of A are <= t guaranteed: sum A[0..15] unconditionally
    float s0 = 0.f, s1 = 0.f;
#pragma unroll
    for (int s = 0; s < 16; s++) { s0 += A[s]; s1 += A[16 + s] <= t ? A[16 + s] : 0.f; }
#pragma unroll
    for (int s = 0; s < 16; s++) s1 += (B[s] <= t) ? B[s] : 0.f;
    mysum = s0 + s1;
  } else {
    // generic rank r = K-1 among 48 non-center values (not taken @epoch 1000)
    int r = K - 1;
    float t = 3.0e38f;
    for (int a = 0; a < 48; a++) {
      float va = vals[a * NT + tid];
      int cnt = 0;
      for (int q = 0; q < 48; q++) cnt += (vals[q * NT + tid] <= va) ? 1 : 0;
      if (cnt >= r) t = fminf(t, va);
    }
    for (int a = 0; a < 48; a++) {
      float va = vals[a * NT + tid];
      mysum += (va <= t) ? va : 0.f;
    }
  }

  // block reduce -> one double atomic
#pragma unroll
  for (int o = 16; o > 0; o >>= 1) mysum += __shfl_down_sync(0xffffffffu, mysum, o);
  if ((tid & 31) == 0) red[tid >> 5] = mysum;
  __syncthreads();
  if (tid == 0) {
    float tot = 0.f;
    for (int w2 = 0; w2 < NT / 32; w2++) tot += red[w2];
    atomicAdd(&g_cl, (double)tot);
  }
}

// ---------------- edge-aware smoothness, split by direction ----------------
__global__ void k_gradx(const float* __restrict__ pred, const float* __restrict__ xin) {
  int idx = blockIdx.x * 256 + threadIdx.x;
  float sx = 0.f;
  if (idx < 2 * CW * CW) {
    int b = idx / (CW * CW);
    int rem = idx - b * (CW * CW);
    int y = CROP + rem / CW;
    int x = CROP + rem % CW;
    if (x < CROP + CW - 1) {
      const float* I = xin + ((size_t)b * 49 + 24) * PLANE;
      const float* D = pred + (size_t)b * W * W;
      size_t o = (size_t)y * W + x;
      float a = fabsf(I[(o + 1) * 3] - I[o * 3]) +
                fabsf(I[(o + 1) * 3 + 1] - I[o * 3 + 1]) +
                fabsf(I[(o + 1) * 3 + 2] - I[o * 3 + 2]);
      sx = expf(-50.f * a) * fabsf(D[o + 1] - D[o]);
    }
  }
#pragma unroll
  for (int o2 = 16; o2 > 0; o2 >>= 1) sx += __shfl_down_sync(0xffffffffu, sx, o2);
  __shared__ float rx[8];
  int tid = threadIdx.x;
  if ((tid & 31) == 0) rx[tid >> 5] = sx;
  __syncthreads();
  if (tid == 0) {
    float a = 0.f;
    for (int w2 = 0; w2 < 8; w2++) a += rx[w2];
    atomicAdd(&g_gx, (double)a);
  }
}

__global__ void k_grady(const float* __restrict__ pred, const float* __restrict__ xin) {
  int idx = blockIdx.x * 256 + threadIdx.x;
  float sy = 0.f;
  if (idx < 2 * CW * CW) {
    int b = idx / (CW * CW);
    int rem = idx - b * (CW * CW);
    int y = CROP + rem / CW;
    int x = CROP + rem % CW;
    if (y < CROP + CW - 1) {
      const float* I = xin + ((size_t)b * 49 + 24) * PLANE;
      const float* D = pred + (size_t)b * W * W;
      size_t o = (size_t)y * W + x;
      float a = fabsf(I[(o + W) * 3] - I[o * 3]) +
                fabsf(I[(o + W) * 3 + 1] - I[o * 3 + 1]) +
                fabsf(I[(o + W) * 3 + 2] - I[o * 3 + 2]);
      sy = expf(-50.f * a) * fabsf(D[o + W] - D[o]);
    }
  }
#pragma unroll
  for (int o2 = 16; o2 > 0; o2 >>= 1) sy += __shfl_down_sync(0xffffffffu, sy, o2);
  __shared__ float ry[8];
  int tid = threadIdx.x;
  if ((tid & 31) == 0) ry[tid >> 5] = sy;
  __syncthreads();
  if (tid == 0) {
    float c = 0.f;
    for (int w2 = 0; w2 < 8; w2++) c += ry[w2];
    atomicAdd(&g_gy, (double)c);
  }
}

__global__ void k_fin(const int* __restrict__ ep, float* __restrict__ out) {
  int epoch = ep ? ep[0] : 1000;
  int K = 49 - k_epoch(epoch);
  double mcl = g_cl / ((double)K * 6.0 * 496.0 * 496.0);
  double den = 2.0 * 496.0 * 495.0;
  double gl = 0.5 * (g_gx / den + g_gy / den);
  out[0] = (float)(mcl + 0.1 * gl);
}

extern "C" void kernel_launch(void* const* d_in, const int* in_sizes, int n_in,
                              void* d_out, int out_size) {
  const float* pred = (const float*)d_in[0];
  const float* x    = (const float*)d_in[1];
  const int*   ep   = (n_in >= 3) ? (const int*)d_in[2] : nullptr;

  cudaFuncSetAttribute(k_main, cudaFuncAttributeMaxDynamicSharedMemorySize, SMEM_BYTES);

  k_init<<<1, 1>>>();
  k_gradx<<<(2 * CW * CW + 255) / 256, 256>>>(pred, x);
  k_grady<<<(2 * CW * CW + 255) / 256, 256>>>(pred, x);
  dim3 grid(31, 62, 2);
  k_main<<<grid, NT, SMEM_BYTES>>>(pred, x, ep);
  k_fin<<<1, 1>>>(ep, (float*)d_out);
}

// round 12
// speedup vs baseline: 1.2686x; 1.1891x over previous
#include <cuda_runtime.h>
#include <cstdint>

#define CROP 8
#define W    512
#define CW   496
#define TX   16
#define TY   16
#define NPIX 256
#define NT   768               /* 256 pixels x 3 channels */
#define SW   22
#define STAGEF (SW*SW*3)       /* 1452 floats per view tile */
#define PLANE  (W*W*3)

__device__ double g_cl, g_gx, g_gy;

__global__ void k_init() { g_cl = 0.0; g_gx = 0.0; g_gy = 0.0; }

__device__ __forceinline__ int k_epoch(int e) {
  if (e < 200) return 0;
  if (e < 2300) return ((e - 200) / 100) * 2;
  return 44;
}

// insert v into sorted-descending top-17 register array
__device__ __forceinline__ void insert17(float (&T)[17], float v) {
#pragma unroll
  for (int i = 0; i < 17; i++) {
    float hi = fmaxf(T[i], v);
    v = fminf(T[i], v);
    T[i] = hi;
  }
}

// bilinear sample of channel ch at (ty,tx) from a staged tile, minus center
__device__ __forceinline__ float bilin_diff(const float* __restrict__ stg,
                                            float ty, float tx,
                                            int row0, int col0, int ch, float cen) {
  float fy = floorf(ty), fx = floorf(tx);
  float wy = ty - fy, wx = tx - fx;
  int iy = (int)fy - row0;
  int ix = (int)fx - col0;
  int base = (iy * SW + ix) * 3 + ch;
  float v00 = stg[base],      v01 = stg[base + 3];
  float v10 = stg[base + 66], v11 = stg[base + 69];
  float a0 = v00 + wx * (v01 - v00);
  float a1 = v10 + wx * (v11 - v10);
  float r  = a0 + wy * (a1 - a0);
  return fabsf(r - cen);
}

__global__ __launch_bounds__(NT, 2)
void k_main(const float* __restrict__ pred, const float* __restrict__ xin,
            const int* __restrict__ ep) {
  __shared__ float stage[2 * STAGEF];   // 11,616 B
  __shared__ float red[NT / 32];

  const int tid = threadIdx.x;
  const int ch  = tid >> 8;            // 0..2
  const int pix = tid & 255;
  const int lx = pix & 15, ly = pix >> 4;
  const int gx0 = CROP + blockIdx.x * TX;
  const int gy0 = CROP + blockIdx.y * TY;
  const int b = blockIdx.z;
  const int gx = gx0 + lx, gy = gy0 + ly;
  const int row0 = gy0 - 3, col0 = gx0 - 3;
  const float* xb = xin + (size_t)b * 49 * PLANE;

  const float p = __ldg(pred + ((size_t)b * W + gy) * W + gx);
  const float fgy = (float)gy, fgx = (float)gx;
  const int epoch = ep ? ep[0] : 1000;
  const int K = 49 - k_epoch(epoch);
  const bool fast = (K == 33);

  // per-thread staging offsets (elements tid, tid+NT of 1452-float tile), 32-bit
  const int sidx0 = tid, sidx1 = tid + NT;
  const int r0 = sidx0 / 66, c0 = sidx0 - r0 * 66;
  const int r1 = sidx1 / 66, c1 = sidx1 - r1 * 66;
  const uint32_t goff0 = (uint32_t)(row0 + r0) * (W * 3) + (uint32_t)(col0 * 3 + c0);
  const uint32_t goff1 = (uint32_t)(row0 + r1) * (W * 3) + (uint32_t)(col0 * 3 + c1);
  const bool ok1 = (sidx1 < STAGEF);

  float loc[48];   // only touched in generic-K path (uniform, never @epoch 1000)

  // ---- stage center view (24) ----
  {
    const float* pl = xb + (size_t)24 * PLANE;
    stage[sidx0] = __ldg(pl + goff0);
    if (ok1) stage[sidx1] = __ldg(pl + goff1);
  }
  __syncthreads();
  const float cen = stage[((ly + 3) * SW + (lx + 3)) * 3 + ch];

  // ---- prefetch pair 0 (views n=0,1) ----
  float ra0, ra1, rb0, rb1;
  {
    const float* pl0 = xb;
    const float* pl1 = xb + (size_t)PLANE;
    ra0 = __ldg(pl0 + goff0);
    ra1 = ok1 ? __ldg(pl0 + goff1) : 0.f;
    rb0 = __ldg(pl1 + goff0);
    rb1 = ok1 ? __ldg(pl1 + goff1) : 0.f;
  }

  float T[17];
#pragma unroll
  for (int i = 0; i < 17; i++) T[i] = -1.0f;
  float total = 0.f;

  for (int j = 0; j < 24; j++) {
    __syncthreads();                 // prior reads of stage complete
    stage[sidx0] = ra0;
    if (ok1) stage[sidx1] = ra1;
    stage[STAGEF + sidx0] = rb0;
    if (ok1) stage[STAGEF + sidx1] = rb1;
    __syncthreads();                 // staged pair visible

    if (j < 23) {                    // prefetch pair j+1
      int s0n = 2 * (j + 1);
      int n0 = (s0n < 24) ? s0n : s0n + 1;
      int n1 = (s0n + 1 < 24) ? s0n + 1 : s0n + 2;
      const float* pl0 = xb + (size_t)n0 * PLANE;
      const float* pl1 = xb + (size_t)n1 * PLANE;
      ra0 = __ldg(pl0 + goff0);
      ra1 = ok1 ? __ldg(pl0 + goff1) : 0.f;
      rb0 = __ldg(pl1 + goff0);
      rb1 = ok1 ? __ldg(pl1 + goff1) : 0.f;
    }

    // compute views s=2j (buffer 0), s=2j+1 (buffer 1)
    {
      int s = 2 * j;
      int n = (s < 24) ? s : s + 1;
      float du = (float)(n / 7 - 3), dv = (float)(n % 7 - 3);
      float ty = __fadd_rn(fgy, __fmul_rn(p, du));
      float tx = __fadd_rn(fgx, __fmul_rn(p, dv));
      float v = bilin_diff(stage, ty, tx, row0, col0, ch, cen);
      total += v;
      insert17(T, v);
      if (!fast) loc[s] = v;
    }
    {
      int s = 2 * j + 1;
      int n = (s < 24) ? s : s + 1;
      float du = (float)(n / 7 - 3), dv = (float)(n % 7 - 3);
      float ty = __fadd_rn(fgy, __fmul_rn(p, du));
      float tx = __fadd_rn(fgx, __fmul_rn(p, dv));
      float v = bilin_diff(stage + STAGEF, ty, tx, row0, col0, ch, cen);
      total += v;
      insert17(T, v);
      if (!fast) loc[s] = v;
    }
  }

  // ---------------- masked-sum epilogue ----------------
  float mysum;
  if (fast) {
    // t = 17th largest of 48 = rank-32 smallest (center's 0 accounted for).
    // masked sum over v <= t: total minus strictly-greater elements.
    float t = T[16];
    float sub = 0.f;
#pragma unroll
    for (int i = 0; i < 16; i++) sub += (T[i] > t) ? T[i] : 0.f;
    mysum = total - sub;
  } else {
    // generic rank r = K-1 among 48 non-center values
    int r = K - 1;
    float t = 3.0e38f;
    for (int a = 0; a < 48; a++) {
      float va = loc[a];
      int cnt = 0;
      for (int q = 0; q < 48; q++) cnt += (loc[q] <= va) ? 1 : 0;
      if (cnt >= r) t = fminf(t, va);
    }
    mysum = 0.f;
    for (int a = 0; a < 48; a++) mysum += (loc[a] <= t) ? loc[a] : 0.f;
  }

  // block reduce -> one double atomic
#pragma unroll
  for (int o = 16; o > 0; o >>= 1) mysum += __shfl_down_sync(0xffffffffu, mysum, o);
  if ((tid & 31) == 0) red[tid >> 5] = mysum;
  __syncthreads();
  if (tid == 0) {
    float tot = 0.f;
    for (int w2 = 0; w2 < NT / 32; w2++) tot += red[w2];
    atomicAdd(&g_cl, (double)tot);
  }
}

// ---------------- edge-aware smoothness, split by direction ----------------
__global__ void k_gradx(const float* __restrict__ pred, const float* __restrict__ xin) {
  int idx = blockIdx.x * 256 + threadIdx.x;
  float sx = 0.f;
  if (idx < 2 * CW * CW) {
    int b = idx / (CW * CW);
    int rem = idx - b * (CW * CW);
    int y = CROP + rem / CW;
    int x = CROP + rem % CW;
    if (x < CROP + CW - 1) {
      const float* I = xin + ((size_t)b * 49 + 24) * PLANE;
      const float* D = pred + (size_t)b * W * W;
      size_t o = (size_t)y * W + x;
      float a = fabsf(I[(o + 1) * 3] - I[o * 3]) +
                fabsf(I[(o + 1) * 3 + 1] - I[o * 3 + 1]) +
                fabsf(I[(o + 1) * 3 + 2] - I[o * 3 + 2]);
      sx = expf(-50.f * a) * fabsf(D[o + 1] - D[o]);
    }
  }
#pragma unroll
  for (int o2 = 16; o2 > 0; o2 >>= 1) sx += __shfl_down_sync(0xffffffffu, sx, o2);
  __shared__ float rx[8];
  int tid = threadIdx.x;
  if ((tid & 31) == 0) rx[tid >> 5] = sx;
  __syncthreads();
  if (tid == 0) {
    float a = 0.f;
    for (int w2 = 0; w2 < 8; w2++) a += rx[w2];
    atomicAdd(&g_gx, (double)a);
  }
}

__global__ void k_grady(const float* __restrict__ pred, const float* __restrict__ xin) {
  int idx = blockIdx.x * 256 + threadIdx.x;
  float sy = 0.f;
  if (idx < 2 * CW * CW) {
    int b = idx / (CW * CW);
    int rem = idx - b * (CW * CW);
    int y = CROP + rem / CW;
    int x = CROP + rem % CW;
    if (y < CROP + CW - 1) {
      const float* I = xin + ((size_t)b * 49 + 24) * PLANE;
      const float* D = pred + (size_t)b * W * W;
      size_t o = (size_t)y * W + x;
      float a = fabsf(I[(o + W) * 3] - I[o * 3]) +
                fabsf(I[(o + W) * 3 + 1] - I[o * 3 + 1]) +
                fabsf(I[(o + W) * 3 + 2] - I[o * 3 + 2]);
      sy = expf(-50.f * a) * fabsf(D[o + W] - D[o]);
    }
  }
#pragma unroll
  for (int o2 = 16; o2 > 0; o2 >>= 1) sy += __shfl_down_sync(0xffffffffu, sy, o2);
  __shared__ float ry[8];
  int tid = threadIdx.x;
  if ((tid & 31) == 0) ry[tid >> 5] = sy;
  __syncthreads();
  if (tid == 0) {
    float c = 0.f;
    for (int w2 = 0; w2 < 8; w2++) c += ry[w2];
    atomicAdd(&g_gy, (double)c);
  }
}

__global__ void k_fin(const int* __restrict__ ep, float* __restrict__ out) {
  int epoch = ep ? ep[0] : 1000;
  int K = 49 - k_epoch(epoch);
  double mcl = g_cl / ((double)K * 6.0 * 496.0 * 496.0);
  double den = 2.0 * 496.0 * 495.0;
  double gl = 0.5 * (g_gx / den + g_gy / den);
  out[0] = (float)(mcl + 0.1 * gl);
}

extern "C" void kernel_launch(void* const* d_in, const int* in_sizes, int n_in,
                              void* d_out, int out_size) {
  const float* pred = (const float*)d_in[0];
  const float* x    = (const float*)d_in[1];
  const int*   ep   = (n_in >= 3) ? (const int*)d_in[2] : nullptr;

  k_init<<<1, 1>>>();
  k_gradx<<<(2 * CW * CW + 255) / 256, 256>>>(pred, x);
  k_grady<<<(2 * CW * CW + 255) / 256, 256>>>(pred, x);
  dim3 grid(31, 31, 2);
  k_main<<<grid, NT>>>(pred, x, ep);
  k_fin<<<1, 1>>>(ep, (float*)d_out);
}